// round 14
// baseline (speedup 1.0000x reference)
#include <cuda_runtime.h>
#include <cuda_bf16.h>
#include <math.h>

#define BATCH 2
#define NSEQ 1536
#define DIMX 1536
#define HEADS 8
#define DK 64
#define HD 512
#define BN 3072
#define NPOS 3071
#define NRPFK 192

typedef unsigned long long u64;
typedef unsigned int u32;

__device__ __forceinline__ u32 smem_u32(const void* p) {
    u32 a;
    asm("{ .reg .u64 t; cvta.to.shared.u64 t, %1; cvt.u32.u64 %0, t; }" : "=r"(a) : "l"(p));
    return a;
}

// ================= warp MMA primitives =================
__device__ __forceinline__ void ldsm4(u32 &r0, u32 &r1, u32 &r2, u32 &r3, u32 addr) {
    asm volatile("ldmatrix.sync.aligned.m8n8.x4.shared.b16 {%0,%1,%2,%3}, [%4];"
                 : "=r"(r0), "=r"(r1), "=r"(r2), "=r"(r3) : "r"(addr));
}
__device__ __forceinline__ void ldsm4t(u32 &r0, u32 &r1, u32 &r2, u32 &r3, u32 addr) {
    asm volatile("ldmatrix.sync.aligned.m8n8.x4.trans.shared.b16 {%0,%1,%2,%3}, [%4];"
                 : "=r"(r0), "=r"(r1), "=r"(r2), "=r"(r3) : "r"(addr));
}
__device__ __forceinline__ void mma16816(float* d, const u32* a, const u32* b) {
    asm volatile("mma.sync.aligned.m16n8k16.row.col.f32.bf16.bf16.f32 "
        "{%0,%1,%2,%3}, {%4,%5,%6,%7}, {%8,%9}, {%0,%1,%2,%3};"
        : "+f"(d[0]), "+f"(d[1]), "+f"(d[2]), "+f"(d[3])
        : "r"(a[0]), "r"(a[1]), "r"(a[2]), "r"(a[3]), "r"(b[0]), "r"(b[1]));
}
__device__ __forceinline__ u32 pack2(float x, float y, u32 &lo) {
    __nv_bfloat16 hx = __float2bfloat16(x), hy = __float2bfloat16(y);
    __nv_bfloat16 lx = __float2bfloat16(x - __bfloat162float(hx));
    __nv_bfloat16 ly = __float2bfloat16(y - __bfloat162float(hy));
    lo = (u32)__bfloat16_as_ushort(lx) | ((u32)__bfloat16_as_ushort(ly) << 16);
    return (u32)__bfloat16_as_ushort(hx) | ((u32)__bfloat16_as_ushort(hy) << 16);
}
__device__ __forceinline__ float bf_lo(u32 w) {
    return __bfloat162float(__ushort_as_bfloat16((unsigned short)(w & 0xffff)));
}
__device__ __forceinline__ float bf_hi(u32 w) {
    return __bfloat162float(__ushort_as_bfloat16((unsigned short)(w >> 16)));
}

// ================= cp.async =================
#define CP16(dst, src) \
    asm volatile("cp.async.cg.shared.global [%0], [%1], 16;" :: "r"(dst), "l"(src) : "memory")
#define CP_COMMIT() asm volatile("cp.async.commit_group;" ::: "memory")
#define CP_WAIT0()  asm volatile("cp.async.wait_group 0;" ::: "memory")
#define CP_WAIT1()  asm volatile("cp.async.wait_group 1;" ::: "memory")

// ================= scratch =================
__device__ __align__(16) float g_k [16 * 1536 * 64];
__device__ __align__(16) float g_v [16 * 1536 * 64];
__device__ __align__(16) float g_relk[3071 * 512];
__device__ __align__(16) __nv_bfloat16 p_xh[3072 * 1536], p_xl[3072 * 1536];
__device__ __align__(16) __nv_bfloat16 p_w3h[3 * 1536 * 512], p_w3l[3 * 1536 * 512];
__device__ __align__(16) __nv_bfloat16 p_woh[512 * 1536], p_wol[512 * 1536];
__device__ __align__(16) __nv_bfloat16 p_peh[3071 * 192], p_pel[3071 * 192];
__device__ __align__(16) __nv_bfloat16 p_wrh[192 * 512], p_wrl[192 * 512];
__device__ __align__(16) u32 p_qch[16 * 1536 * 32], p_qcl[16 * 1536 * 32];
__device__ __align__(16) u32 p_qrh[16 * 1536 * 32], p_qrl[16 * 1536 * 32];
__device__ __align__(16) u32 p_kh [16 * 1536 * 32], p_kl [16 * 1536 * 32];
__device__ __align__(16) u32 p_vh [16 * 1536 * 32], p_vl [16 * 1536 * 32];
__device__ __align__(16) u32 p_rbh[3071 * 256], p_rbl[3071 * 256];
__device__ __align__(16) u32 p_aoh[3072 * 256], p_aol[3072 * 256];

// ================= fused pack kernel =================
#define PACK_BLOCKS 8352
__global__ void pack_all(const float4* __restrict__ x,  const float4* __restrict__ wq,
                         const float4* __restrict__ wk, const float4* __restrict__ wv,
                         const float4* __restrict__ wo, const float4* __restrict__ pe,
                         const float4* __restrict__ wr)
{
    int blk = blockIdx.x;
    const float4* src; u64* dh; u64* dl; int n4, b0;
    if (blk < 4608)      { src = x;  dh = (u64*)p_xh;           dl = (u64*)p_xl;           n4 = 1179648; b0 = 0; }
    else if (blk < 5376) { src = wq; dh = (u64*)p_w3h;          dl = (u64*)p_w3l;          n4 = 196608;  b0 = 4608; }
    else if (blk < 6144) { src = wk; dh = (u64*)p_w3h + 196608; dl = (u64*)p_w3l + 196608; n4 = 196608;  b0 = 5376; }
    else if (blk < 6912) { src = wv; dh = (u64*)p_w3h + 393216; dl = (u64*)p_w3l + 393216; n4 = 196608;  b0 = 6144; }
    else if (blk < 7680) { src = wo; dh = (u64*)p_woh;          dl = (u64*)p_wol;          n4 = 196608;  b0 = 6912; }
    else if (blk < 8256) { src = pe; dh = (u64*)p_peh;          dl = (u64*)p_pel;          n4 = 147408;  b0 = 7680; }
    else                 { src = wr; dh = (u64*)p_wrh;          dl = (u64*)p_wrl;          n4 = 24576;   b0 = 8256; }
    int i = (blk - b0) * 256 + threadIdx.x;
    if (i >= n4) return;
    float4 v = src[i];
    u32 l0, l1;
    u32 h0 = pack2(v.x, v.y, l0);
    u32 h1 = pack2(v.z, v.w, l1);
    dh[i] = (u64)h0 | ((u64)h1 << 32);
    dl[i] = (u64)l0 | ((u64)l1 << 32);
}

// ================= GEMM tiling =================
#define BK 32
#define SA_STRIDE 80
#define SA_BYTES (128 * SA_STRIDE)
#define SB_BYTES (BK * 256)
#define STAGE_BYTES (2 * SA_BYTES + 2 * SB_BYTES)
#define OFF_A_HI(s) ((s) * STAGE_BYTES)
#define OFF_A_LO(s) (OFF_A_HI(s) + SA_BYTES)
#define OFF_B_HI(s) (OFF_A_HI(s) + 2 * SA_BYTES)
#define OFF_B_LO(s) (OFF_B_HI(s) + SB_BYTES)
#define GEMM_SMEM (2 * STAGE_BYTES)

__device__ __forceinline__ void mma_chunk(float (&C)[2][8][4], int s, u32 smb)
{
    const int lane = threadIdx.x & 31, wid = threadIdx.x >> 5;
    const int wm = (wid >> 1) * 32, wn = (wid & 1) * 64;
    const u32 aoff[3] = { smb + (u32)OFF_A_HI(s), smb + (u32)OFF_A_HI(s), smb + (u32)OFF_A_LO(s) };
    const u32 boff[3] = { smb + (u32)OFF_B_HI(s), smb + (u32)OFF_B_LO(s), smb + (u32)OFF_B_HI(s) };

    #pragma unroll
    for (int ks = 0; ks < 2; ks++) {
        const int kb = ks * 16;
        #pragma unroll
        for (int p = 0; p < 3; p++) {
            u32 A0[4], A1[4], Bf[8][2];
            {
                int m = wm + (lane & 15);
                int kk = kb + 8 * (lane >> 4);
                ldsm4(A0[0], A0[1], A0[2], A0[3], aoff[p] + m * SA_STRIDE + kk * 2);
                ldsm4(A1[0], A1[1], A1[2], A1[3], aoff[p] + (m + 16) * SA_STRIDE + kk * 2);
            }
            {
                int krow = kb + ((lane >> 3) & 1) * 8 + (lane & 7);
                int nofs = ((lane >> 4) & 1) * 8;
                int kx = krow & 7;
                #pragma unroll
                for (int pr = 0; pr < 4; pr++) {
                    int n = wn + pr * 16 + nofs;
                    u32 addr = boff[p] + krow * 256 + (((n >> 3) ^ kx) << 4);
                    ldsm4t(Bf[2 * pr][0], Bf[2 * pr][1], Bf[2 * pr + 1][0], Bf[2 * pr + 1][1], addr);
                }
            }
            #pragma unroll
            for (int j = 0; j < 8; j++) {
                mma16816(C[0][j], A0, Bf[j]);
                mma16816(C[1][j], A1, Bf[j]);
            }
        }
    }
}

__device__ __forceinline__ void gemm_mma_pk(float (&C)[2][8][4],
    const __nv_bfloat16* __restrict__ Ah, const __nv_bfloat16* __restrict__ Al,
    int lda, int Mg, int m0,
    const __nv_bfloat16* __restrict__ Bh, const __nv_bfloat16* __restrict__ Bl,
    int ldb, int n0, int K, u32 smb)
{
    const int NC = K / BK;
    const int tid = threadIdx.x;

    auto load_async = [&](int s, int kc) {
        #pragma unroll
        for (int rep = 0; rep < 2; rep++) {
            int v = tid + rep * 256;
            int row = v >> 2, part = v & 3;
            int sr = m0 + row; if (sr > Mg - 1) sr = Mg - 1;
            const char* sh = (const char*)(Ah + (size_t)sr * lda + kc * BK) + part * 16;
            const char* sl = (const char*)(Al + (size_t)sr * lda + kc * BK) + part * 16;
            u32 d = (u32)(row * SA_STRIDE + part * 16);
            CP16(smb + OFF_A_HI(s) + d, sh);
            CP16(smb + OFF_A_LO(s) + d, sl);
        }
        {
            int k = tid >> 3, g = tid & 7;
            int kx = k & 7;
            const char* rh = (const char*)(Bh + (size_t)(kc * BK + k) * ldb + n0);
            const char* rl = (const char*)(Bl + (size_t)(kc * BK + k) * ldb + n0);
            #pragma unroll
            for (int hf = 0; hf < 2; hf++) {
                int gg = g + hf * 8;
                u32 d = (u32)(k * 256 + ((gg ^ kx) << 4));
                CP16(smb + OFF_B_HI(s) + d, rh + gg * 16);
                CP16(smb + OFF_B_LO(s) + d, rl + gg * 16);
            }
        }
        CP_COMMIT();
    };

    load_async(0, 0);
    for (int c = 0; c < NC; c++) {
        int s = c & 1;
        if (c + 1 < NC) { load_async(s ^ 1, c + 1); CP_WAIT1(); }
        else            { CP_WAIT0(); }
        __syncthreads();
        mma_chunk(C, s, smb);
        __syncthreads();
    }
}

// ================= fused QKV + relk GEMM kernel =================
__global__ __launch_bounds__(256) void qkvrelk_tc(
    const float* __restrict__ rcb, const float* __restrict__ rpb)
{
    extern __shared__ char smc[];
    u32 smb = smem_u32(smc);
    const int z = blockIdx.z;
    const int m0 = blockIdx.y * 128, n0 = blockIdx.x * 128;

    float C[2][8][4];
    #pragma unroll
    for (int a = 0; a < 2; a++)
        #pragma unroll
        for (int b = 0; b < 8; b++)
            #pragma unroll
            for (int q = 0; q < 4; q++) C[a][b][q] = 0.f;

    const int lane = threadIdx.x & 31, wid = threadIdx.x >> 5;
    const int wm = m0 + (wid >> 1) * 32, wn = n0 + (wid & 1) * 64;

    if (z < 3) {
        gemm_mma_pk(C, p_xh, p_xl, DIMX, BN, m0,
                    p_w3h + (size_t)z * DIMX * HD, p_w3l + (size_t)z * DIMX * HD,
                    HD, n0, DIMX, smb);
        #pragma unroll
        for (int t2 = 0; t2 < 2; t2++)
            #pragma unroll
            for (int j = 0; j < 8; j++)
                #pragma unroll
                for (int hf = 0; hf < 2; hf++) {
                    int gm = wm + 16 * t2 + (lane >> 2) + 8 * hf;
                    int gn = wn + 8 * j + 2 * (lane & 3);
                    float v0 = C[t2][j][2 * hf], v1 = C[t2][j][2 * hf + 1];
                    int bb = gm / NSEQ, ii = gm - bb * NSEQ;
                    int hh = gn >> 6, dd = gn & 63;
                    size_t i32 = ((size_t)(bb * HEADS + hh) * NSEQ + ii) * 32 + (dd >> 1);
                    if (z == 0) {
                        float2 cb = *(const float2*)&rcb[gn];
                        float2 pb = *(const float2*)&rpb[gn];
                        u32 lo, hi;
                        hi = pack2(v0 * 0.125f + cb.x, v1 * 0.125f + cb.y, lo);
                        p_qch[i32] = hi; p_qcl[i32] = lo;
                        hi = pack2(v0 * 0.125f + pb.x, v1 * 0.125f + pb.y, lo);
                        p_qrh[i32] = hi; p_qrl[i32] = lo;
                    } else {
                        size_t idx = ((size_t)(bb * HEADS + hh) * NSEQ + ii) * DK + dd;
                        u32 lo, hi = pack2(v0, v1, lo);
                        if (z == 1) {
                            *(float2*)&g_k[idx] = make_float2(v0, v1);
                            p_kh[i32] = hi; p_kl[i32] = lo;
                        } else {
                            *(float2*)&g_v[idx] = make_float2(v0, v1);
                            p_vh[i32] = hi; p_vl[i32] = lo;
                        }
                    }
                }
    } else {
        gemm_mma_pk(C, p_peh, p_pel, NRPFK, NPOS, m0, p_wrh, p_wrl, HD, n0, NRPFK, smb);
        #pragma unroll
        for (int t2 = 0; t2 < 2; t2++)
            #pragma unroll
            for (int j = 0; j < 8; j++)
                #pragma unroll
                for (int hf = 0; hf < 2; hf++) {
                    int gm = wm + 16 * t2 + (lane >> 2) + 8 * hf;
                    int gn = wn + 8 * j + 2 * (lane & 3);
                    if (gm < NPOS) {
                        float v0 = C[t2][j][2 * hf], v1 = C[t2][j][2 * hf + 1];
                        *(float2*)&g_relk[(size_t)gm * HD + gn] = make_float2(v0, v1);
                        u32 lo, hi = pack2(v0, v1, lo);
                        size_t i32 = (size_t)gm * 256 + (gn >> 1);
                        p_rbh[i32] = hi; p_rbl[i32] = lo;
                    }
                }
    }
}

__global__ __launch_bounds__(256) void out_tc(
    const float* __restrict__ bo, float* __restrict__ out)
{
    extern __shared__ char smc[];
    u32 smb = smem_u32(smc);
    const int m0 = blockIdx.y * 128, n0 = blockIdx.x * 128;

    float C[2][8][4];
    #pragma unroll
    for (int a = 0; a < 2; a++)
        #pragma unroll
        for (int b = 0; b < 8; b++)
            #pragma unroll
            for (int q = 0; q < 4; q++) C[a][b][q] = 0.f;

    gemm_mma_pk(C, (const __nv_bfloat16*)p_aoh, (const __nv_bfloat16*)p_aol, HD, BN, m0,
                p_woh, p_wol, DIMX, n0, HD, smb);

    const int lane = threadIdx.x & 31, wid = threadIdx.x >> 5;
    const int wm = m0 + (wid >> 1) * 32, wn = n0 + (wid & 1) * 64;
    #pragma unroll
    for (int t2 = 0; t2 < 2; t2++)
        #pragma unroll
        for (int j = 0; j < 8; j++)
            #pragma unroll
            for (int hf = 0; hf < 2; hf++) {
                int gm = wm + 16 * t2 + (lane >> 2) + 8 * hf;
                int gn = wn + 8 * j + 2 * (lane & 3);
                float2 bv = *(const float2*)&bo[gn];
                *(float2*)&out[(size_t)gm * DIMX + gn] =
                    make_float2(C[t2][j][2 * hf] + bv.x, C[t2][j][2 * hf + 1] + bv.y);
            }
}

// ================= tensorized block-sparse attention =================
// R13 structure + windowed T (per-warp 80-row band; Q stays in smem)
#define AT_QCH 0
#define AT_QCL 9216
#define AT_QRH 18432
#define AT_QRL 27648
#define AT_ST(s) (36864 + (s) * 73728)
#define ST_KH  0
#define ST_KL  9216
#define ST_VH  18432
#define ST_VL  27648
#define ST_RBH 36864
#define ST_RBL 55296
#define AT_T   184320
#define AT_TW_STRIDE 5376              // 16*84*4 per warp
#define ATTN_SMEM (184320 + 64 * 132 * 4)   // 218112

__device__ __forceinline__ void ldA_frag(u32* A, u32 base, int row0, int kk, int lane) {
    u32 addr = base + (u32)((row0 + (lane & 15)) * 144 + (kk * 16 + ((lane >> 4) << 3)) * 2);
    ldsm4(A[0], A[1], A[2], A[3], addr);
}
__device__ __forceinline__ void ldB_rows(u32* B4, u32 base, int nb, int kk, int lane) {
    int n = nb * 16 + (lane & 7) + ((lane >> 4) & 1) * 8;
    int ko = kk * 16 + ((lane >> 3) & 1) * 8;
    ldsm4(B4[0], B4[1], B4[2], B4[3], base + (u32)(n * 144 + ko * 2));
}
__device__ __forceinline__ void ldB_vt(u32* B4, u32 base, int nb, int kk, int lane) {
    int kr = kk * 16 + (lane & 7) + ((lane >> 3) & 1) * 8;
    int nofs = nb * 16 + ((lane >> 4) & 1) * 8;
    ldsm4t(B4[0], B4[1], B4[2], B4[3], base + (u32)(kr * 144 + nofs * 2));
}

__global__ __launch_bounds__(128) void attn_kernel()
{
    extern __shared__ char smc[];
    u32 smb = smem_u32(smc);
    float* Tsm = (float*)(smc + AT_T);

    const int bh = blockIdx.x;
    const int qt = blockIdx.y;
    const int b  = bh >> 3, h = bh & 7;
    const int i0 = qt * 64;
    const int tid = threadIdx.x;
    const int lane = tid & 31, wid = tid >> 5;
    const int wm = wid * 16;
    const int il1 = lane >> 2, il2 = il1 + 8;
    const int i1 = wm + il1, i2 = wm + il2;
    const int cq = 2 * (lane & 3);

    float* Tw = Tsm + wid * (AT_TW_STRIDE / 4);     // per-warp [16][84]
    const float* kg  = g_k + (size_t)bh * NSEQ * DK;
    const float* vg  = g_v + (size_t)bh * NSEQ * DK;

    const int bi = qt >> 1;
    int lo, hi;
    if (bi == 0) { lo = 0; hi = 3; }
    else { lo = (bi - 1) * 2; hi = ((bi < 11) ? (bi + 1) : 11) * 2 + 1; }
    const bool do_mini = (lo > 0);
    const bool do_glob = (qt == 0);
    const int rbase = 48 - wm;          // warp band window start

    auto prefetch = [&](int s, int j0) {
        u32 base = smb + (u32)AT_ST(s);
        {
            int row = tid >> 1, jo = (tid & 1) * 16;
            size_t gk = (size_t)(bh * NSEQ + j0 + row) * 32 + jo;
            u32 d = (u32)(row * 144 + jo * 4);
            #pragma unroll
            for (int i = 0; i < 4; i++) {
                CP16(base + ST_KH + d + i * 16, (const char*)(p_kh + gk + i * 4));
                CP16(base + ST_KL + d + i * 16, (const char*)(p_kl + gk + i * 4));
                CP16(base + ST_VH + d + i * 16, (const char*)(p_vh + gk + i * 4));
                CP16(base + ST_VL + d + i * 16, (const char*)(p_vl + gk + i * 4));
            }
        }
        if (tid < 127) {
            const int gbase = (j0 - i0) + 1472;
            size_t gb = (size_t)(gbase + tid) * 256 + h * 32;
            u32 d = (u32)(tid * 144);
            #pragma unroll
            for (int i = 0; i < 8; i++) {
                CP16(base + ST_RBH + d + i * 16, (const char*)(p_rbh + gb + i * 4));
                CP16(base + ST_RBL + d + i * 16, (const char*)(p_rbl + gb + i * 4));
            }
        }
        CP_COMMIT();
    };

    if (tid < 32) {
        int s = tid >> 4, pl = (tid >> 3) & 1, i = tid & 7;
        *(uint4*)(smc + AT_ST(s) + (pl ? ST_RBL : ST_RBH) + 127 * 144 + i * 16) =
            make_uint4(0, 0, 0, 0);
    }

    prefetch(0, lo * 64);
    {
        int row = tid >> 1, jo = (tid & 1) * 16;
        size_t gq = (size_t)(bh * NSEQ + i0 + row) * 32 + jo;
        const uint4* sq0 = (const uint4*)(p_qch + gq);
        const uint4* sq1 = (const uint4*)(p_qcl + gq);
        const uint4* sq2 = (const uint4*)(p_qrh + gq);
        const uint4* sq3 = (const uint4*)(p_qrl + gq);
        uint4* d0 = (uint4*)(smc + AT_QCH + row * 144 + jo * 4);
        uint4* d1 = (uint4*)(smc + AT_QCL + row * 144 + jo * 4);
        uint4* d2 = (uint4*)(smc + AT_QRH + row * 144 + jo * 4);
        uint4* d3 = (uint4*)(smc + AT_QRL + row * 144 + jo * 4);
        #pragma unroll
        for (int i = 0; i < 4; i++) {
            d0[i] = sq0[i]; d1[i] = sq1[i]; d2[i] = sq2[i]; d3[i] = sq3[i];
        }
    }

    float m_i[2] = {-1e30f, -1e30f}, l_i[2] = {0.f, 0.f};
    float O[8][4];
    #pragma unroll
    for (int f = 0; f < 8; f++)
        #pragma unroll
        for (int e = 0; e < 4; e++) O[f][e] = 0.f;

    int stage = 0;
    for (int t = lo; t <= hi; t++) {
        CP_WAIT0();
        __syncthreads();
        if (t < hi) prefetch(stage ^ 1, (t + 1) * 64);

        const u32 base = smb + (u32)AT_ST(stage);

        // ---- S = Qc.K^T ----
        float Sc[8][4];
        #pragma unroll
        for (int f = 0; f < 8; f++)
            #pragma unroll
            for (int e = 0; e < 4; e++) Sc[f][e] = 0.f;

        #pragma unroll
        for (int kk = 0; kk < 4; kk++) {
            u32 Ah[4], Al[4];
            ldA_frag(Ah, smb + AT_QCH, wm, kk, lane);
            ldA_frag(Al, smb + AT_QCL, wm, kk, lane);
            #pragma unroll
            for (int nb = 0; nb < 4; nb++) {
                u32 bhf[4], blf[4];
                ldB_rows(bhf, base + ST_KH, nb, kk, lane);
                ldB_rows(blf, base + ST_KL, nb, kk, lane);
                mma16816(Sc[2 * nb], Ah, bhf);     mma16816(Sc[2 * nb + 1], Ah, bhf + 2);
                mma16816(Sc[2 * nb], Ah, blf);     mma16816(Sc[2 * nb + 1], Ah, blf + 2);
                mma16816(Sc[2 * nb], Al, bhf);     mma16816(Sc[2 * nb + 1], Al, bhf + 2);
            }
        }

        // ---- T = Qr.RB^T restricted to warp's 80-row band window ----
        #pragma unroll
        for (int nb = 0; nb < 5; nb++) {
            float Tr2[2][4];
            #pragma unroll
            for (int ff = 0; ff < 2; ff++)
                #pragma unroll
                for (int e = 0; e < 4; e++) Tr2[ff][e] = 0.f;
            #pragma unroll
            for (int kk = 0; kk < 4; kk++) {
                u32 Ah[4], Al[4];
                ldA_frag(Ah, smb + AT_QRH, wm, kk, lane);
                ldA_frag(Al, smb + AT_QRL, wm, kk, lane);
                int n = rbase + nb * 16 + (lane & 7) + ((lane >> 4) & 1) * 8;
                int ko = kk * 16 + ((lane >> 3) & 1) * 8;
                u32 bhf[4], blf[4];
                ldsm4(bhf[0], bhf[1], bhf[2], bhf[3], base + ST_RBH + (u32)(n * 144 + ko * 2));
                ldsm4(blf[0], blf[1], blf[2], blf[3], base + ST_RBL + (u32)(n * 144 + ko * 2));
                mma16816(Tr2[0], Ah, bhf);     mma16816(Tr2[1], Ah, bhf + 2);
                mma16816(Tr2[0], Ah, blf);     mma16816(Tr2[1], Ah, blf + 2);
                mma16816(Tr2[0], Al, bhf);     mma16816(Tr2[1], Al, bhf + 2);
            }
            #pragma unroll
            for (int ff = 0; ff < 2; ff++) {
                int c = nb * 16 + 8 * ff + cq;
                *(float2*)&Tw[il1 * 84 + c] = make_float2(Tr2[ff][0], Tr2[ff][1]);
                *(float2*)&Tw[il2 * 84 + c] = make_float2(Tr2[ff][2], Tr2[ff][3]);
            }
        }
        __syncwarp();

        // ---- combine: S[i][j] += T window gather ----
        #pragma unroll
        for (int f = 0; f < 8; f++) {
            int jc = 8 * f + cq;
            Sc[f][0] += Tw[il1 * 84 + jc - il1 + 15];
            Sc[f][1] += Tw[il1 * 84 + jc - il1 + 16];
            Sc[f][2] += Tw[il2 * 84 + jc - il2 + 15];
            Sc[f][3] += Tw[il2 * 84 + jc - il2 + 16];
        }

        // ---- online softmax ----
        float mx0 = -1e30f, mx1 = -1e30f;
        #pragma unroll
        for (int f = 0; f < 8; f++) {
            mx0 = fmaxf(mx0, fmaxf(Sc[f][0], Sc[f][1]));
            mx1 = fmaxf(mx1, fmaxf(Sc[f][2], Sc[f][3]));
        }
        mx0 = fmaxf(mx0, __shfl_xor_sync(0xffffffffu, mx0, 1));
        mx0 = fmaxf(mx0, __shfl_xor_sync(0xffffffffu, mx0, 2));
        mx1 = fmaxf(mx1, __shfl_xor_sync(0xffffffffu, mx1, 1));
        mx1 = fmaxf(mx1, __shfl_xor_sync(0xffffffffu, mx1, 2));
        float mn0 = fmaxf(m_i[0], mx0), mn1 = fmaxf(m_i[1], mx1);
        float s0 = 0.f, s1 = 0.f;
        #pragma unroll
        for (int f = 0; f < 8; f++) {
            Sc[f][0] = __expf(Sc[f][0] - mn0); s0 += Sc[f][0];
            Sc[f][1] = __expf(Sc[f][1] - mn0); s0 += Sc[f][1];
            Sc[f][2] = __expf(Sc[f][2] - mn1); s1 += Sc[f][2];
            Sc[f][3] = __expf(Sc[f][3] - mn1); s1 += Sc[f][3];
        }
        s0 += __shfl_xor_sync(0xffffffffu, s0, 1);
        s0 += __shfl_xor_sync(0xffffffffu, s0, 2);
        s1 += __shfl_xor_sync(0xffffffffu, s1, 1);
        s1 += __shfl_xor_sync(0xffffffffu, s1, 2);
        float c0 = __expf(m_i[0] - mn0), c1 = __expf(m_i[1] - mn1);
        l_i[0] = l_i[0] * c0 + s0;  m_i[0] = mn0;
        l_i[1] = l_i[1] * c1 + s1;  m_i[1] = mn1;
        #pragma unroll
        for (int f = 0; f < 8; f++) {
            O[f][0] *= c0; O[f][1] *= c0;
            O[f][2] *= c1; O[f][3] *= c1;
        }

        // ---- O += P.V ----
        #pragma unroll
        for (int kt = 0; kt < 4; kt++) {
            u32 Ph[4], Pl[4];
            Ph[0] = pack2(Sc[2 * kt][0],     Sc[2 * kt][1],     Pl[0]);
            Ph[1] = pack2(Sc[2 * kt][2],     Sc[2 * kt][3],     Pl[1]);
            Ph[2] = pack2(Sc[2 * kt + 1][0], Sc[2 * kt + 1][1], Pl[2]);
            Ph[3] = pack2(Sc[2 * kt + 1][2], Sc[2 * kt + 1][3], Pl[3]);
            #pragma unroll
            for (int nb = 0; nb < 4; nb++) {
                u32 vh[4], vl[4];
                ldB_vt(vh, base + ST_VH, nb, kt, lane);
                ldB_vt(vl, base + ST_VL, nb, kt, lane);
                mma16816(O[2 * nb], Ph, vh);     mma16816(O[2 * nb + 1], Ph, vh + 2);
                mma16816(O[2 * nb], Ph, vl);     mma16816(O[2 * nb + 1], Ph, vl + 2);
                mma16816(O[2 * nb], Pl, vh);     mma16816(O[2 * nb + 1], Pl, vh + 2);
            }
        }
        stage ^= 1;
    }

    // ---- mini-phase: global columns 0..3 (qt >= 4) ----
    if (do_mini) {
        const int ig1 = i0 + i1, ig2 = i0 + i2;
        const __nv_bfloat16* QCH = (const __nv_bfloat16*)(smc + AT_QCH);
        const __nv_bfloat16* QCL = (const __nv_bfloat16*)(smc + AT_QCL);
        const __nv_bfloat16* QRH = (const __nv_bfloat16*)(smc + AT_QRH);
        const __nv_bfloat16* QRL = (const __nv_bfloat16*)(smc + AT_QRL);
        float sA[4] = {0.f, 0.f, 0.f, 0.f}, sB[4] = {0.f, 0.f, 0.f, 0.f};
        const float* rl1 = g_relk + (size_t)(1535 - ig1) * HD + h * DK;
        const float* rl2 = g_relk + (size_t)(1535 - ig2) * HD + h * DK;
        for (int d = 0; d < 64; d++) {
            float qc1 = __bfloat162float(QCH[i1 * 72 + d]) + __bfloat162float(QCL[i1 * 72 + d]);
            float qr1 = __bfloat162float(QRH[i1 * 72 + d]) + __bfloat162float(QRL[i1 * 72 + d]);
            float qc2 = __bfloat162float(QCH[i2 * 72 + d]) + __bfloat162float(QCL[i2 * 72 + d]);
            float qr2 = __bfloat162float(QRH[i2 * 72 + d]) + __bfloat162float(QRL[i2 * 72 + d]);
            #pragma unroll
            for (int c = 0; c < 4; c++) {
                float kv = kg[c * 64 + d];
                sA[c] += qc1 * kv + qr1 * rl1[c * HD + d];
                sB[c] += qc2 * kv + qr2 * rl2[c * HD + d];
            }
        }
        {
            float mx = fmaxf(fmaxf(sA[0], sA[1]), fmaxf(sA[2], sA[3]));
            float mn = fmaxf(m_i[0], mx);
            float cr = __expf(m_i[0] - mn);
            float p[4], ps = 0.f;
            #pragma unroll
            for (int c = 0; c < 4; c++) { p[c] = __expf(sA[c] - mn); ps += p[c]; }
            l_i[0] = l_i[0] * cr + ps; m_i[0] = mn;
            #pragma unroll
            for (int f = 0; f < 8; f++)
                #pragma unroll
                for (int e = 0; e < 2; e++) {
                    int d = 8 * f + cq + e;
                    float acc = O[f][e] * cr;
                    #pragma unroll
                    for (int c = 0; c < 4; c++) acc += p[c] * vg[c * 64 + d];
                    O[f][e] = acc;
                }
        }
        {
            float mx = fmaxf(fmaxf(sB[0], sB[1]), fmaxf(sB[2], sB[3]));
            float mn = fmaxf(m_i[1], mx);
            float cr = __expf(m_i[1] - mn);
            float p[4], ps = 0.f;
            #pragma unroll
            for (int c = 0; c < 4; c++) { p[c] = __expf(sB[c] - mn); ps += p[c]; }
            l_i[1] = l_i[1] * cr + ps; m_i[1] = mn;
            #pragma unroll
            for (int f = 0; f < 8; f++)
                #pragma unroll
                for (int e = 0; e < 2; e++) {
                    int d = 8 * f + cq + e;
                    float acc = O[f][2 + e] * cr;
                    #pragma unroll
                    for (int c = 0; c < 4; c++) acc += p[c] * vg[c * 64 + d];
                    O[f][2 + e] = acc;
                }
        }
    }

    // ---- dense phase (qt==0) ----
    if (do_glob) {
        __syncthreads();
        float* Sx  = Tsm;
        float* Qf  = Tsm + 5120;
        float* O2  = Qf + 512;
        float* ML  = O2 + 256;
        float* wst = ML + 8;

        {
            const __nv_bfloat16* QCH = (const __nv_bfloat16*)(smc + AT_QCH);
            const __nv_bfloat16* QCL = (const __nv_bfloat16*)(smc + AT_QCL);
            const __nv_bfloat16* QRH = (const __nv_bfloat16*)(smc + AT_QRH);
            const __nv_bfloat16* QRL = (const __nv_bfloat16*)(smc + AT_QRL);
            #pragma unroll
            for (int u = 0; u < 4; u++) {
                int idx = tid * 4 + u;
                int r = idx >> 6, d = idx & 63;
                float v;
                if (r < 4)
                    v = __bfloat162float(QCH[r * 72 + d]) + __bfloat162float(QCL[r * 72 + d]);
                else
                    v = __bfloat162float(QRH[(r - 4) * 72 + d]) + __bfloat162float(QRL[(r - 4) * 72 + d]);
                Qf[idx] = v;
            }
        }
        __syncthreads();

        float mloc[4] = {-1e30f, -1e30f, -1e30f, -1e30f};
        #pragma unroll
        for (int u = 0; u < 10; u++) {
            int jloc = u * 128 + tid;
            int j = 256 + jloc;
            const float* kr = kg + j * 64;
            const float* rl = g_relk + (size_t)(j + 1535) * HD + h * DK;
            float a0 = 0.f, a1 = 0.f, a2 = 0.f, a3 = 0.f;
            #pragma unroll 8
            for (int d = 0; d < 64; d++) {
                float kv = kr[d];
                a0 += Qf[d] * kv        + Qf[256 + d] * rl[d];
                a1 += Qf[64 + d] * kv   + Qf[320 + d] * rl[d - HD];
                a2 += Qf[128 + d] * kv  + Qf[384 + d] * rl[d - 2 * HD];
                a3 += Qf[192 + d] * kv  + Qf[448 + d] * rl[d - 3 * HD];
            }
            Sx[jloc] = a0; Sx[1280 + jloc] = a1;
            Sx[2560 + jloc] = a2; Sx[3840 + jloc] = a3;
            mloc[0] = fmaxf(mloc[0], a0); mloc[1] = fmaxf(mloc[1], a1);
            mloc[2] = fmaxf(mloc[2], a2); mloc[3] = fmaxf(mloc[3], a3);
        }
        #pragma unroll
        for (int r = 0; r < 4; r++)
            #pragma unroll
            for (int off = 16; off >= 1; off >>= 1)
                mloc[r] = fmaxf(mloc[r], __shfl_xor_sync(0xffffffffu, mloc[r], off));
        if (lane == 0)
            #pragma unroll
            for (int r = 0; r < 4; r++) wst[wid * 4 + r] = mloc[r];
        __syncthreads();
        if (tid < 4) {
            float m = -1e30f;
            #pragma unroll
            for (int w = 0; w < 4; w++) m = fmaxf(m, wst[w * 4 + tid]);
            ML[tid] = m;
        }
        __syncthreads();
        float M2r[4] = {ML[0], ML[1], ML[2], ML[3]};
        float lloc[4] = {0.f, 0.f, 0.f, 0.f};
        #pragma unroll
        for (int u = 0; u < 10; u++) {
            int jloc = u * 128 + tid;
            #pragma unroll
            for (int r = 0; r < 4; r++) {
                float p = __expf(Sx[r * 1280 + jloc] - M2r[r]);
                Sx[r * 1280 + jloc] = p;
                lloc[r] += p;
            }
        }
        #pragma unroll
        for (int r = 0; r < 4; r++)
            #pragma unroll
            for (int off = 16; off >= 1; off >>= 1)
                lloc[r] += __shfl_xor_sync(0xffffffffu, lloc[r], off);
        if (lane == 0)
            #pragma unroll
            for (int r = 0; r < 4; r++) wst[wid * 4 + r] = lloc[r];
        __syncthreads();
        if (tid < 4) {
            float s = 0.f;
            #pragma unroll
            for (int w = 0; w < 4; w++) s += wst[w * 4 + tid];
            ML[4 + tid] = s;
        }
        __syncthreads();

        #pragma unroll
        for (int u = 0; u < 2; u++) {
            int idx = u * 128 + tid;
            int r = idx >> 6, d = idx & 63;
            const float* vp = vg + 256 * 64 + d;
            const float* px = Sx + r * 1280;
            float o = 0.f;
            #pragma unroll 4
            for (int jj = 0; jj < 1280; jj++)
                o += px[jj] * vp[jj * 64];
            O2[r * 64 + d] = o;
        }
        __syncthreads();

        if (wid == 0 && (lane >> 2) < 4) {
            int r = lane >> 2;
            float M2v = ML[r], L2v = ML[4 + r];
            float mn = fmaxf(m_i[0], M2v);
            float cA = __expf(m_i[0] - mn);
            float cB = __expf(M2v - mn);
            l_i[0] = l_i[0] * cA + L2v * cB;
            m_i[0] = mn;
            #pragma unroll
            for (int f = 0; f < 8; f++)
                #pragma unroll
                for (int e = 0; e < 2; e++) {
                    int d = 8 * f + cq + e;
                    O[f][e] = O[f][e] * cA + O2[r * 64 + d] * cB;
                }
        }
    }

    // ---- normalize + write packed ao ----
    {
        float inv0 = 1.f / l_i[0], inv1 = 1.f / l_i[1];
        size_t o1 = (size_t)(b * NSEQ + i0 + i1) * 256 + h * 32;
        size_t o2 = (size_t)(b * NSEQ + i0 + i2) * 256 + h * 32;
        #pragma unroll
        for (int f = 0; f < 8; f++) {
            int j = (8 * f + cq) >> 1;
            u32 lo, hi;
            hi = pack2(O[f][0] * inv0, O[f][1] * inv0, lo);
            p_aoh[o1 + j] = hi; p_aol[o1 + j] = lo;
            hi = pack2(O[f][2] * inv1, O[f][3] * inv1, lo);
            p_aoh[o2 + j] = hi; p_aol[o2 + j] = lo;
        }
    }
}

// ================= launch =================
extern "C" void kernel_launch(void* const* d_in, const int* in_sizes, int n_in,
                              void* d_out, int out_size)
{
    const float* x    = (const float*)d_in[0];
    const float* Wq   = (const float*)d_in[1];
    const float* Wk   = (const float*)d_in[2];
    const float* Wv   = (const float*)d_in[3];
    const float* Wrel = (const float*)d_in[4];
    const float* rcb  = (const float*)d_in[5];
    const float* rpb  = (const float*)d_in[6];
    const float* Wo   = (const float*)d_in[7];
    const float* bo   = (const float*)d_in[8];
    const float* pe   = (const float*)d_in[9];
    float* out = (float*)d_out;

    cudaFuncSetAttribute(attn_kernel, cudaFuncAttributeMaxDynamicSharedMemorySize, ATTN_SMEM);
    cudaFuncSetAttribute(qkvrelk_tc, cudaFuncAttributeMaxDynamicSharedMemorySize, GEMM_SMEM);
    cudaFuncSetAttribute(out_tc,     cudaFuncAttributeMaxDynamicSharedMemorySize, GEMM_SMEM);

    pack_all<<<PACK_BLOCKS, 256>>>((const float4*)x, (const float4*)Wq, (const float4*)Wk,
                                   (const float4*)Wv, (const float4*)Wo, (const float4*)pe,
                                   (const float4*)Wrel);
    qkvrelk_tc<<<dim3(4, 24, 4), 256, GEMM_SMEM>>>(rcb, rpb);
    attn_kernel<<<dim3(16, 24), 128, ATTN_SMEM>>>();
    out_tc<<<dim3(12, 24), 256, GEMM_SMEM>>>(bo, out);
}

// round 15
// speedup vs baseline: 1.1455x; 1.1455x over previous
#include <cuda_runtime.h>
#include <cuda_bf16.h>
#include <math.h>

#define BATCH 2
#define NSEQ 1536
#define DIMX 1536
#define HEADS 8
#define DK 64
#define HD 512
#define BN 3072
#define NPOS 3071
#define NRPFK 192

typedef unsigned long long u64;
typedef unsigned int u32;

__device__ __forceinline__ u32 smem_u32(const void* p) {
    u32 a;
    asm("{ .reg .u64 t; cvta.to.shared.u64 t, %1; cvt.u32.u64 %0, t; }" : "=r"(a) : "l"(p));
    return a;
}

// ================= warp MMA primitives =================
__device__ __forceinline__ void ldsm4(u32 &r0, u32 &r1, u32 &r2, u32 &r3, u32 addr) {
    asm volatile("ldmatrix.sync.aligned.m8n8.x4.shared.b16 {%0,%1,%2,%3}, [%4];"
                 : "=r"(r0), "=r"(r1), "=r"(r2), "=r"(r3) : "r"(addr));
}
__device__ __forceinline__ void ldsm4t(u32 &r0, u32 &r1, u32 &r2, u32 &r3, u32 addr) {
    asm volatile("ldmatrix.sync.aligned.m8n8.x4.trans.shared.b16 {%0,%1,%2,%3}, [%4];"
                 : "=r"(r0), "=r"(r1), "=r"(r2), "=r"(r3) : "r"(addr));
}
__device__ __forceinline__ void mma16816(float* d, const u32* a, const u32* b) {
    asm volatile("mma.sync.aligned.m16n8k16.row.col.f32.bf16.bf16.f32 "
        "{%0,%1,%2,%3}, {%4,%5,%6,%7}, {%8,%9}, {%0,%1,%2,%3};"
        : "+f"(d[0]), "+f"(d[1]), "+f"(d[2]), "+f"(d[3])
        : "r"(a[0]), "r"(a[1]), "r"(a[2]), "r"(a[3]), "r"(b[0]), "r"(b[1]));
}
__device__ __forceinline__ u32 pack2(float x, float y, u32 &lo) {
    __nv_bfloat16 hx = __float2bfloat16(x), hy = __float2bfloat16(y);
    __nv_bfloat16 lx = __float2bfloat16(x - __bfloat162float(hx));
    __nv_bfloat16 ly = __float2bfloat16(y - __bfloat162float(hy));
    lo = (u32)__bfloat16_as_ushort(lx) | ((u32)__bfloat16_as_ushort(ly) << 16);
    return (u32)__bfloat16_as_ushort(hx) | ((u32)__bfloat16_as_ushort(hy) << 16);
}
__device__ __forceinline__ float bf_lo(u32 w) {
    return __bfloat162float(__ushort_as_bfloat16((unsigned short)(w & 0xffff)));
}
__device__ __forceinline__ float bf_hi(u32 w) {
    return __bfloat162float(__ushort_as_bfloat16((unsigned short)(w >> 16)));
}

// ================= cp.async =================
#define CP16(dst, src) \
    asm volatile("cp.async.cg.shared.global [%0], [%1], 16;" :: "r"(dst), "l"(src) : "memory")
#define CP_COMMIT() asm volatile("cp.async.commit_group;" ::: "memory")
#define CP_WAIT0()  asm volatile("cp.async.wait_group 0;" ::: "memory")
#define CP_WAIT1()  asm volatile("cp.async.wait_group 1;" ::: "memory")
#define BAR_SYNC(id, cnt) asm volatile("bar.sync %0, %1;" :: "r"(id), "r"(cnt) : "memory")

// ================= scratch =================
__device__ __align__(16) float g_k [16 * 1536 * 64];
__device__ __align__(16) float g_v [16 * 1536 * 64];
__device__ __align__(16) float g_relk[3071 * 512];
__device__ __align__(16) __nv_bfloat16 p_xh[3072 * 1536], p_xl[3072 * 1536];
__device__ __align__(16) __nv_bfloat16 p_w3h[3 * 1536 * 512], p_w3l[3 * 1536 * 512];
__device__ __align__(16) __nv_bfloat16 p_woh[512 * 1536], p_wol[512 * 1536];
__device__ __align__(16) __nv_bfloat16 p_peh[3071 * 192], p_pel[3071 * 192];
__device__ __align__(16) __nv_bfloat16 p_wrh[192 * 512], p_wrl[192 * 512];
__device__ __align__(16) u32 p_qch[16 * 1536 * 32], p_qcl[16 * 1536 * 32];
__device__ __align__(16) u32 p_qrh[16 * 1536 * 32], p_qrl[16 * 1536 * 32];
__device__ __align__(16) u32 p_kh [16 * 1536 * 32], p_kl [16 * 1536 * 32];
__device__ __align__(16) u32 p_vh [16 * 1536 * 32], p_vl [16 * 1536 * 32];
__device__ __align__(16) u32 p_rbh[3071 * 256], p_rbl[3071 * 256];
__device__ __align__(16) u32 p_aoh[3072 * 256], p_aol[3072 * 256];

// ================= fused pack kernel =================
#define PACK_BLOCKS 8352
__global__ void pack_all(const float4* __restrict__ x,  const float4* __restrict__ wq,
                         const float4* __restrict__ wk, const float4* __restrict__ wv,
                         const float4* __restrict__ wo, const float4* __restrict__ pe,
                         const float4* __restrict__ wr)
{
    int blk = blockIdx.x;
    const float4* src; u64* dh; u64* dl; int n4, b0;
    if (blk < 4608)      { src = x;  dh = (u64*)p_xh;           dl = (u64*)p_xl;           n4 = 1179648; b0 = 0; }
    else if (blk < 5376) { src = wq; dh = (u64*)p_w3h;          dl = (u64*)p_w3l;          n4 = 196608;  b0 = 4608; }
    else if (blk < 6144) { src = wk; dh = (u64*)p_w3h + 196608; dl = (u64*)p_w3l + 196608; n4 = 196608;  b0 = 5376; }
    else if (blk < 6912) { src = wv; dh = (u64*)p_w3h + 393216; dl = (u64*)p_w3l + 393216; n4 = 196608;  b0 = 6144; }
    else if (blk < 7680) { src = wo; dh = (u64*)p_woh;          dl = (u64*)p_wol;          n4 = 196608;  b0 = 6912; }
    else if (blk < 8256) { src = pe; dh = (u64*)p_peh;          dl = (u64*)p_pel;          n4 = 147408;  b0 = 7680; }
    else                 { src = wr; dh = (u64*)p_wrh;          dl = (u64*)p_wrl;          n4 = 24576;   b0 = 8256; }
    int i = (blk - b0) * 256 + threadIdx.x;
    if (i >= n4) return;
    float4 v = src[i];
    u32 l0, l1;
    u32 h0 = pack2(v.x, v.y, l0);
    u32 h1 = pack2(v.z, v.w, l1);
    dh[i] = (u64)h0 | ((u64)h1 << 32);
    dl[i] = (u64)l0 | ((u64)l1 << 32);
}

// ================= GEMM tiling =================
#define BK 32
#define SA_STRIDE 80
#define SA_BYTES (128 * SA_STRIDE)
#define SB_BYTES (BK * 256)
#define STAGE_BYTES (2 * SA_BYTES + 2 * SB_BYTES)
#define OFF_A_HI(s) ((s) * STAGE_BYTES)
#define OFF_A_LO(s) (OFF_A_HI(s) + SA_BYTES)
#define OFF_B_HI(s) (OFF_A_HI(s) + 2 * SA_BYTES)
#define OFF_B_LO(s) (OFF_B_HI(s) + SB_BYTES)
#define GEMM_SMEM (2 * STAGE_BYTES)

__device__ __forceinline__ void mma_chunk(float (&C)[2][8][4], int s, u32 smb)
{
    const int lane = threadIdx.x & 31, wid = threadIdx.x >> 5;
    const int wm = (wid >> 1) * 32, wn = (wid & 1) * 64;
    const u32 aoff[3] = { smb + (u32)OFF_A_HI(s), smb + (u32)OFF_A_HI(s), smb + (u32)OFF_A_LO(s) };
    const u32 boff[3] = { smb + (u32)OFF_B_HI(s), smb + (u32)OFF_B_LO(s), smb + (u32)OFF_B_HI(s) };

    #pragma unroll
    for (int ks = 0; ks < 2; ks++) {
        const int kb = ks * 16;
        #pragma unroll
        for (int p = 0; p < 3; p++) {
            u32 A0[4], A1[4], Bf[8][2];
            {
                int m = wm + (lane & 15);
                int kk = kb + 8 * (lane >> 4);
                ldsm4(A0[0], A0[1], A0[2], A0[3], aoff[p] + m * SA_STRIDE + kk * 2);
                ldsm4(A1[0], A1[1], A1[2], A1[3], aoff[p] + (m + 16) * SA_STRIDE + kk * 2);
            }
            {
                int krow = kb + ((lane >> 3) & 1) * 8 + (lane & 7);
                int nofs = ((lane >> 4) & 1) * 8;
                int kx = krow & 7;
                #pragma unroll
                for (int pr = 0; pr < 4; pr++) {
                    int n = wn + pr * 16 + nofs;
                    u32 addr = boff[p] + krow * 256 + (((n >> 3) ^ kx) << 4);
                    ldsm4t(Bf[2 * pr][0], Bf[2 * pr][1], Bf[2 * pr + 1][0], Bf[2 * pr + 1][1], addr);
                }
            }
            #pragma unroll
            for (int j = 0; j < 8; j++) {
                mma16816(C[0][j], A0, Bf[j]);
                mma16816(C[1][j], A1, Bf[j]);
            }
        }
    }
}

__device__ __forceinline__ void gemm_mma_pk(float (&C)[2][8][4],
    const __nv_bfloat16* __restrict__ Ah, const __nv_bfloat16* __restrict__ Al,
    int lda, int Mg, int m0,
    const __nv_bfloat16* __restrict__ Bh, const __nv_bfloat16* __restrict__ Bl,
    int ldb, int n0, int K, u32 smb)
{
    const int NC = K / BK;
    const int tid = threadIdx.x;

    auto load_async = [&](int s, int kc) {
        #pragma unroll
        for (int rep = 0; rep < 2; rep++) {
            int v = tid + rep * 256;
            int row = v >> 2, part = v & 3;
            int sr = m0 + row; if (sr > Mg - 1) sr = Mg - 1;
            const char* sh = (const char*)(Ah + (size_t)sr * lda + kc * BK) + part * 16;
            const char* sl = (const char*)(Al + (size_t)sr * lda + kc * BK) + part * 16;
            u32 d = (u32)(row * SA_STRIDE + part * 16);
            CP16(smb + OFF_A_HI(s) + d, sh);
            CP16(smb + OFF_A_LO(s) + d, sl);
        }
        {
            int k = tid >> 3, g = tid & 7;
            int kx = k & 7;
            const char* rh = (const char*)(Bh + (size_t)(kc * BK + k) * ldb + n0);
            const char* rl = (const char*)(Bl + (size_t)(kc * BK + k) * ldb + n0);
            #pragma unroll
            for (int hf = 0; hf < 2; hf++) {
                int gg = g + hf * 8;
                u32 d = (u32)(k * 256 + ((gg ^ kx) << 4));
                CP16(smb + OFF_B_HI(s) + d, rh + gg * 16);
                CP16(smb + OFF_B_LO(s) + d, rl + gg * 16);
            }
        }
        CP_COMMIT();
    };

    load_async(0, 0);
    for (int c = 0; c < NC; c++) {
        int s = c & 1;
        if (c + 1 < NC) { load_async(s ^ 1, c + 1); CP_WAIT1(); }
        else            { CP_WAIT0(); }
        __syncthreads();
        mma_chunk(C, s, smb);
        __syncthreads();
    }
}

// ================= fused QKV + relk GEMM kernel =================
__global__ __launch_bounds__(256) void qkvrelk_tc(
    const float* __restrict__ rcb, const float* __restrict__ rpb)
{
    extern __shared__ char smc[];
    u32 smb = smem_u32(smc);
    const int z = blockIdx.z;
    const int m0 = blockIdx.y * 128, n0 = blockIdx.x * 128;

    float C[2][8][4];
    #pragma unroll
    for (int a = 0; a < 2; a++)
        #pragma unroll
        for (int b = 0; b < 8; b++)
            #pragma unroll
            for (int q = 0; q < 4; q++) C[a][b][q] = 0.f;

    const int lane = threadIdx.x & 31, wid = threadIdx.x >> 5;
    const int wm = m0 + (wid >> 1) * 32, wn = n0 + (wid & 1) * 64;

    if (z < 3) {
        gemm_mma_pk(C, p_xh, p_xl, DIMX, BN, m0,
                    p_w3h + (size_t)z * DIMX * HD, p_w3l + (size_t)z * DIMX * HD,
                    HD, n0, DIMX, smb);
        #pragma unroll
        for (int t2 = 0; t2 < 2; t2++)
            #pragma unroll
            for (int j = 0; j < 8; j++)
                #pragma unroll
                for (int hf = 0; hf < 2; hf++) {
                    int gm = wm + 16 * t2 + (lane >> 2) + 8 * hf;
                    int gn = wn + 8 * j + 2 * (lane & 3);
                    float v0 = C[t2][j][2 * hf], v1 = C[t2][j][2 * hf + 1];
                    int bb = gm / NSEQ, ii = gm - bb * NSEQ;
                    int hh = gn >> 6, dd = gn & 63;
                    size_t i32 = ((size_t)(bb * HEADS + hh) * NSEQ + ii) * 32 + (dd >> 1);
                    if (z == 0) {
                        float2 cb = *(const float2*)&rcb[gn];
                        float2 pb = *(const float2*)&rpb[gn];
                        u32 lo, hi;
                        hi = pack2(v0 * 0.125f + cb.x, v1 * 0.125f + cb.y, lo);
                        p_qch[i32] = hi; p_qcl[i32] = lo;
                        hi = pack2(v0 * 0.125f + pb.x, v1 * 0.125f + pb.y, lo);
                        p_qrh[i32] = hi; p_qrl[i32] = lo;
                    } else {
                        size_t idx = ((size_t)(bb * HEADS + hh) * NSEQ + ii) * DK + dd;
                        u32 lo, hi = pack2(v0, v1, lo);
                        if (z == 1) {
                            *(float2*)&g_k[idx] = make_float2(v0, v1);
                            p_kh[i32] = hi; p_kl[i32] = lo;
                        } else {
                            *(float2*)&g_v[idx] = make_float2(v0, v1);
                            p_vh[i32] = hi; p_vl[i32] = lo;
                        }
                    }
                }
    } else {
        gemm_mma_pk(C, p_peh, p_pel, NRPFK, NPOS, m0, p_wrh, p_wrl, HD, n0, NRPFK, smb);
        #pragma unroll
        for (int t2 = 0; t2 < 2; t2++)
            #pragma unroll
            for (int j = 0; j < 8; j++)
                #pragma unroll
                for (int hf = 0; hf < 2; hf++) {
                    int gm = wm + 16 * t2 + (lane >> 2) + 8 * hf;
                    int gn = wn + 8 * j + 2 * (lane & 3);
                    if (gm < NPOS) {
                        float v0 = C[t2][j][2 * hf], v1 = C[t2][j][2 * hf + 1];
                        *(float2*)&g_relk[(size_t)gm * HD + gn] = make_float2(v0, v1);
                        u32 lo, hi = pack2(v0, v1, lo);
                        size_t i32 = (size_t)gm * 256 + (gn >> 1);
                        p_rbh[i32] = hi; p_rbl[i32] = lo;
                    }
                }
    }
}

__global__ __launch_bounds__(256) void out_tc(
    const float* __restrict__ bo, float* __restrict__ out)
{
    extern __shared__ char smc[];
    u32 smb = smem_u32(smc);
    const int m0 = blockIdx.y * 128, n0 = blockIdx.x * 128;

    float C[2][8][4];
    #pragma unroll
    for (int a = 0; a < 2; a++)
        #pragma unroll
        for (int b = 0; b < 8; b++)
            #pragma unroll
            for (int q = 0; q < 4; q++) C[a][b][q] = 0.f;

    gemm_mma_pk(C, (const __nv_bfloat16*)p_aoh, (const __nv_bfloat16*)p_aol, HD, BN, m0,
                p_woh, p_wol, DIMX, n0, HD, smb);

    const int lane = threadIdx.x & 31, wid = threadIdx.x >> 5;
    const int wm = m0 + (wid >> 1) * 32, wn = n0 + (wid & 1) * 64;
    #pragma unroll
    for (int t2 = 0; t2 < 2; t2++)
        #pragma unroll
        for (int j = 0; j < 8; j++)
            #pragma unroll
            for (int hf = 0; hf < 2; hf++) {
                int gm = wm + 16 * t2 + (lane >> 2) + 8 * hf;
                int gn = wn + 8 * j + 2 * (lane & 3);
                float2 bv = *(const float2*)&bo[gn];
                *(float2*)&out[(size_t)gm * DIMX + gn] =
                    make_float2(C[t2][j][2 * hf] + bv.x, C[t2][j][2 * hf + 1] + bv.y);
            }
}

// ================= tensorized block-sparse attention =================
// 256 threads, 2 warp-groups split key tiles; flash-merge at end
#define AT_QCH 0
#define AT_QCL 9216
#define AT_QRH 18432
#define AT_QRL 27648
#define AT_ST(s) (36864 + (s) * 73728)
#define ST_KH  0
#define ST_KL  9216
#define ST_VH  18432
#define ST_VL  27648
#define ST_RBH 36864
#define ST_RBL 55296
#define AT_T   184320
#define AT_TW_STRIDE 5376              // 16*84*4 per warp (8 warps)
#define ATTN_SMEM (184320 + 8 * 5376)  // 227328

__device__ __forceinline__ void ldA_frag(u32* A, u32 base, int row0, int kk, int lane) {
    u32 addr = base + (u32)((row0 + (lane & 15)) * 144 + (kk * 16 + ((lane >> 4) << 3)) * 2);
    ldsm4(A[0], A[1], A[2], A[3], addr);
}
__device__ __forceinline__ void ldB_rows(u32* B4, u32 base, int nb, int kk, int lane) {
    int n = nb * 16 + (lane & 7) + ((lane >> 4) & 1) * 8;
    int ko = kk * 16 + ((lane >> 3) & 1) * 8;
    ldsm4(B4[0], B4[1], B4[2], B4[3], base + (u32)(n * 144 + ko * 2));
}
__device__ __forceinline__ void ldB_vt(u32* B4, u32 base, int nb, int kk, int lane) {
    int kr = kk * 16 + (lane & 7) + ((lane >> 3) & 1) * 8;
    int nofs = nb * 16 + ((lane >> 4) & 1) * 8;
    ldsm4t(B4[0], B4[1], B4[2], B4[3], base + (u32)(kr * 144 + nofs * 2));
}

__global__ __launch_bounds__(256) void attn_kernel()
{
    extern __shared__ char smc[];
    u32 smb = smem_u32(smc);
    float* Tsm = (float*)(smc + AT_T);

    const int bh = blockIdx.x;
    const int qt = blockIdx.y;
    const int b  = bh >> 3, h = bh & 7;
    const int i0 = qt * 64;
    const int tid = threadIdx.x;
    const int lane = tid & 31, wid = tid >> 5;
    const int wg = wid >> 2;            // warp group (tile parity)
    const int w4 = wid & 3;             // row-group warp
    const int ltid = tid & 127;         // thread within group
    const int wm = w4 * 16;
    const int il1 = lane >> 2, il2 = il1 + 8;
    const int i1 = wm + il1, i2 = wm + il2;
    const int cq = 2 * (lane & 3);

    float* Tw = Tsm + wid * (AT_TW_STRIDE / 4);     // per-warp [16][84]
    const float* kg  = g_k + (size_t)bh * NSEQ * DK;
    const float* vg  = g_v + (size_t)bh * NSEQ * DK;

    const int bi = qt >> 1;
    int lo, hi;
    if (bi == 0) { lo = 0; hi = 3; }
    else { lo = (bi - 1) * 2; hi = ((bi < 11) ? (bi + 1) : 11) * 2 + 1; }
    const bool do_mini = (lo > 0);
    const bool do_glob = (qt == 0);
    const int rbase = 48 - wm;

    // per-group prefetch of its stage buffer (stage == wg)
    auto prefetch = [&](int j0) {
        u32 base = smb + (u32)AT_ST(wg);
        {
            int row = ltid >> 1, jo = (ltid & 1) * 16;
            size_t gk = (size_t)(bh * NSEQ + j0 + row) * 32 + jo;
            u32 d = (u32)(row * 144 + jo * 4);
            #pragma unroll
            for (int i = 0; i < 4; i++) {
                CP16(base + ST_KH + d + i * 16, (const char*)(p_kh + gk + i * 4));
                CP16(base + ST_KL + d + i * 16, (const char*)(p_kl + gk + i * 4));
                CP16(base + ST_VH + d + i * 16, (const char*)(p_vh + gk + i * 4));
                CP16(base + ST_VL + d + i * 16, (const char*)(p_vl + gk + i * 4));
            }
        }
        if (ltid < 127) {
            const int gbase = (j0 - i0) + 1472;
            size_t gb = (size_t)(gbase + ltid) * 256 + h * 32;
            u32 d = (u32)(ltid * 144);
            #pragma unroll
            for (int i = 0; i < 8; i++) {
                CP16(base + ST_RBH + d + i * 16, (const char*)(p_rbh + gb + i * 4));
                CP16(base + ST_RBL + d + i * 16, (const char*)(p_rbl + gb + i * 4));
            }
        }
        CP_COMMIT();
    };

    // zero row 127 of rel band in both stages (once)
    if (tid < 32) {
        int s = tid >> 4, pl = (tid >> 3) & 1, i = tid & 7;
        *(uint4*)(smc + AT_ST(s) + (pl ? ST_RBL : ST_RBH) + 127 * 144 + i * 16) =
            make_uint4(0, 0, 0, 0);
    }

    // group's first tile
    const int t0 = lo + wg;
    if (t0 <= hi) prefetch(t0 * 64);

    // stage Q (all 256 threads)
    {
        int row = tid >> 2, part = (tid & 3) * 8;
        size_t gq = (size_t)(bh * NSEQ + i0 + row) * 32 + part;
        u32 d = (u32)(row * 144 + part * 4);
        *(uint4*)(smc + AT_QCH + d) = *(const uint4*)(p_qch + gq);
        *(uint4*)(smc + AT_QCH + d + 16) = *(const uint4*)(p_qch + gq + 4);
        *(uint4*)(smc + AT_QCL + d) = *(const uint4*)(p_qcl + gq);
        *(uint4*)(smc + AT_QCL + d + 16) = *(const uint4*)(p_qcl + gq + 4);
        *(uint4*)(smc + AT_QRH + d) = *(const uint4*)(p_qrh + gq);
        *(uint4*)(smc + AT_QRH + d + 16) = *(const uint4*)(p_qrh + gq + 4);
        *(uint4*)(smc + AT_QRL + d) = *(const uint4*)(p_qrl + gq);
        *(uint4*)(smc + AT_QRL + d + 16) = *(const uint4*)(p_qrl + gq + 4);
    }
    __syncthreads();

    float m_i[2] = {-1e30f, -1e30f}, l_i[2] = {0.f, 0.f};
    float O[8][4];
    #pragma unroll
    for (int f = 0; f < 8; f++)
        #pragma unroll
        for (int e = 0; e < 4; e++) O[f][e] = 0.f;

    const u32 base = smb + (u32)AT_ST(wg);
    const int barid = 1 + wg;

    for (int t = t0; t <= hi; t += 2) {
        CP_WAIT0();
        BAR_SYNC(barid, 128);

        // ---- S = Qc.K^T ----
        float Sc[8][4];
        #pragma unroll
        for (int f = 0; f < 8; f++)
            #pragma unroll
            for (int e = 0; e < 4; e++) Sc[f][e] = 0.f;

        #pragma unroll
        for (int kk = 0; kk < 4; kk++) {
            u32 Ah[4], Al[4];
            ldA_frag(Ah, smb + AT_QCH, wm, kk, lane);
            ldA_frag(Al, smb + AT_QCL, wm, kk, lane);
            #pragma unroll
            for (int nb = 0; nb < 4; nb++) {
                u32 bhf[4], blf[4];
                ldB_rows(bhf, base + ST_KH, nb, kk, lane);
                ldB_rows(blf, base + ST_KL, nb, kk, lane);
                mma16816(Sc[2 * nb], Ah, bhf);     mma16816(Sc[2 * nb + 1], Ah, bhf + 2);
                mma16816(Sc[2 * nb], Ah, blf);     mma16816(Sc[2 * nb + 1], Ah, blf + 2);
                mma16816(Sc[2 * nb], Al, bhf);     mma16816(Sc[2 * nb + 1], Al, bhf + 2);
            }
        }

        // ---- T = Qr.RB^T over warp's 80-row band window ----
        #pragma unroll
        for (int nb = 0; nb < 5; nb++) {
            float Tr2[2][4];
            #pragma unroll
            for (int ff = 0; ff < 2; ff++)
                #pragma unroll
                for (int e = 0; e < 4; e++) Tr2[ff][e] = 0.f;
            #pragma unroll
            for (int kk = 0; kk < 4; kk++) {
                u32 Ah[4], Al[4];
                ldA_frag(Ah, smb + AT_QRH, wm, kk, lane);
                ldA_frag(Al, smb + AT_QRL, wm, kk, lane);
                int n = rbase + nb * 16 + (lane & 7) + ((lane >> 4) & 1) * 8;
                int ko = kk * 16 + ((lane >> 3) & 1) * 8;
                u32 bhf[4], blf[4];
                ldsm4(bhf[0], bhf[1], bhf[2], bhf[3], base + ST_RBH + (u32)(n * 144 + ko * 2));
                ldsm4(blf[0], blf[1], blf[2], blf[3], base + ST_RBL + (u32)(n * 144 + ko * 2));
                mma16816(Tr2[0], Ah, bhf);     mma16816(Tr2[1], Ah, bhf + 2);
                mma16816(Tr2[0], Ah, blf);     mma16816(Tr2[1], Ah, blf + 2);
                mma16816(Tr2[0], Al, bhf);     mma16816(Tr2[1], Al, bhf + 2);
            }
            #pragma unroll
            for (int ff = 0; ff < 2; ff++) {
                int c = nb * 16 + 8 * ff + cq;
                *(float2*)&Tw[il1 * 84 + c] = make_float2(Tr2[ff][0], Tr2[ff][1]);
                *(float2*)&Tw[il2 * 84 + c] = make_float2(Tr2[ff][2], Tr2[ff][3]);
            }
        }
        __syncwarp();

        #pragma unroll
        for (int f = 0; f < 8; f++) {
            int jc = 8 * f + cq;
            Sc[f][0] += Tw[il1 * 84 + jc - il1 + 15];
            Sc[f][1] += Tw[il1 * 84 + jc - il1 + 16];
            Sc[f][2] += Tw[il2 * 84 + jc - il2 + 15];
            Sc[f][3] += Tw[il2 * 84 + jc - il2 + 16];
        }

        // ---- online softmax ----
        float mx0 = -1e30f, mx1 = -1e30f;
        #pragma unroll
        for (int f = 0; f < 8; f++) {
            mx0 = fmaxf(mx0, fmaxf(Sc[f][0], Sc[f][1]));
            mx1 = fmaxf(mx1, fmaxf(Sc[f][2], Sc[f][3]));
        }
        mx0 = fmaxf(mx0, __shfl_xor_sync(0xffffffffu, mx0, 1));
        mx0 = fmaxf(mx0, __shfl_xor_sync(0xffffffffu, mx0, 2));
        mx1 = fmaxf(mx1, __shfl_xor_sync(0xffffffffu, mx1, 1));
        mx1 = fmaxf(mx1, __shfl_xor_sync(0xffffffffu, mx1, 2));
        float mn0 = fmaxf(m_i[0], mx0), mn1 = fmaxf(m_i[1], mx1);
        float s0 = 0.f, s1 = 0.f;
        #pragma unroll
        for (int f = 0; f < 8; f++) {
            Sc[f][0] = __expf(Sc[f][0] - mn0); s0 += Sc[f][0];
            Sc[f][1] = __expf(Sc[f][1] - mn0); s0 += Sc[f][1];
            Sc[f][2] = __expf(Sc[f][2] - mn1); s1 += Sc[f][2];
            Sc[f][3] = __expf(Sc[f][3] - mn1); s1 += Sc[f][3];
        }
        s0 += __shfl_xor_sync(0xffffffffu, s0, 1);
        s0 += __shfl_xor_sync(0xffffffffu, s0, 2);
        s1 += __shfl_xor_sync(0xffffffffu, s1, 1);
        s1 += __shfl_xor_sync(0xffffffffu, s1, 2);
        float c0 = __expf(m_i[0] - mn0), c1 = __expf(m_i[1] - mn1);
        l_i[0] = l_i[0] * c0 + s0;  m_i[0] = mn0;
        l_i[1] = l_i[1] * c1 + s1;  m_i[1] = mn1;
        #pragma unroll
        for (int f = 0; f < 8; f++) {
            O[f][0] *= c0; O[f][1] *= c0;
            O[f][2] *= c1; O[f][3] *= c1;
        }

        // ---- O += P.V ----
        #pragma unroll
        for (int kt = 0; kt < 4; kt++) {
            u32 Ph[4], Pl[4];
            Ph[0] = pack2(Sc[2 * kt][0],     Sc[2 * kt][1],     Pl[0]);
            Ph[1] = pack2(Sc[2 * kt][2],     Sc[2 * kt][3],     Pl[1]);
            Ph[2] = pack2(Sc[2 * kt + 1][0], Sc[2 * kt + 1][1], Pl[2]);
            Ph[3] = pack2(Sc[2 * kt + 1][2], Sc[2 * kt + 1][3], Pl[3]);
            #pragma unroll
            for (int nb = 0; nb < 4; nb++) {
                u32 vh[4], vl[4];
                ldB_vt(vh, base + ST_VH, nb, kt, lane);
                ldB_vt(vl, base + ST_VL, nb, kt, lane);
                mma16816(O[2 * nb], Ph, vh);     mma16816(O[2 * nb + 1], Ph, vh + 2);
                mma16816(O[2 * nb], Ph, vl);     mma16816(O[2 * nb + 1], Ph, vl + 2);
                mma16816(O[2 * nb], Pl, vh);     mma16816(O[2 * nb + 1], Pl, vh + 2);
            }
        }

        // prefetch own next tile (all group reads for this tile are done)
        BAR_SYNC(barid, 128);
        if (t + 2 <= hi) prefetch((t + 2) * 64);
    }

    // ---- merge group 1 state into group 0 ----
    __syncthreads();
    {
        float* X = Tsm;   // exchange buffer (Tw dead)
        if (wg == 1) {
            float* p = X + ltid * 36;
            p[0] = m_i[0]; p[1] = m_i[1]; p[2] = l_i[0]; p[3] = l_i[1];
            #pragma unroll
            for (int f = 0; f < 8; f++)
                #pragma unroll
                for (int e = 0; e < 4; e++) p[4 + f * 4 + e] = O[f][e];
        }
        __syncthreads();
        if (wg == 0) {
            const float* p = X + ltid * 36;
            float mg0 = p[0], mg1 = p[1], lg0 = p[2], lg1 = p[3];
            float mn0 = fmaxf(m_i[0], mg0), mn1 = fmaxf(m_i[1], mg1);
            float cA0 = __expf(m_i[0] - mn0), cB0 = __expf(mg0 - mn0);
            float cA1 = __expf(m_i[1] - mn1), cB1 = __expf(mg1 - mn1);
            l_i[0] = l_i[0] * cA0 + lg0 * cB0;  m_i[0] = mn0;
            l_i[1] = l_i[1] * cA1 + lg1 * cB1;  m_i[1] = mn1;
            #pragma unroll
            for (int f = 0; f < 8; f++) {
                O[f][0] = O[f][0] * cA0 + p[4 + f * 4 + 0] * cB0;
                O[f][1] = O[f][1] * cA0 + p[4 + f * 4 + 1] * cB0;
                O[f][2] = O[f][2] * cA1 + p[4 + f * 4 + 2] * cB1;
                O[f][3] = O[f][3] * cA1 + p[4 + f * 4 + 3] * cB1;
            }
        }
    }

    // ---- mini-phase: global columns 0..3 (qt >= 4), group 0 only ----
    if (do_mini && wg == 0) {
        const int ig1 = i0 + i1, ig2 = i0 + i2;
        const __nv_bfloat16* QCH = (const __nv_bfloat16*)(smc + AT_QCH);
        const __nv_bfloat16* QCL = (const __nv_bfloat16*)(smc + AT_QCL);
        const __nv_bfloat16* QRH = (const __nv_bfloat16*)(smc + AT_QRH);
        const __nv_bfloat16* QRL = (const __nv_bfloat16*)(smc + AT_QRL);
        float sA[4] = {0.f, 0.f, 0.f, 0.f}, sB[4] = {0.f, 0.f, 0.f, 0.f};
        const float* rl1 = g_relk + (size_t)(1535 - ig1) * HD + h * DK;
        const float* rl2 = g_relk + (size_t)(1535 - ig2) * HD + h * DK;
        for (int d = 0; d < 64; d++) {
            float qc1 = __bfloat162float(QCH[i1 * 72 + d]) + __bfloat162float(QCL[i1 * 72 + d]);
            float qr1 = __bfloat162float(QRH[i1 * 72 + d]) + __bfloat162float(QRL[i1 * 72 + d]);
            float qc2 = __bfloat162float(QCH[i2 * 72 + d]) + __bfloat162float(QCL[i2 * 72 + d]);
            float qr2 = __bfloat162float(QRH[i2 * 72 + d]) + __bfloat162float(QRL[i2 * 72 + d]);
            #pragma unroll
            for (int c = 0; c < 4; c++) {
                float kv = kg[c * 64 + d];
                sA[c] += qc1 * kv + qr1 * rl1[c * HD + d];
                sB[c] += qc2 * kv + qr2 * rl2[c * HD + d];
            }
        }
        {
            float mx = fmaxf(fmaxf(sA[0], sA[1]), fmaxf(sA[2], sA[3]));
            float mn = fmaxf(m_i[0], mx);
            float cr = __expf(m_i[0] - mn);
            float p[4], ps = 0.f;
            #pragma unroll
            for (int c = 0; c < 4; c++) { p[c] = __expf(sA[c] - mn); ps += p[c]; }
            l_i[0] = l_i[0] * cr + ps; m_i[0] = mn;
            #pragma unroll
            for (int f = 0; f < 8; f++)
                #pragma unroll
                for (int e = 0; e < 2; e++) {
                    int d = 8 * f + cq + e;
                    float acc = O[f][e] * cr;
                    #pragma unroll
                    for (int c = 0; c < 4; c++) acc += p[c] * vg[c * 64 + d];
                    O[f][e] = acc;
                }
        }
        {
            float mx = fmaxf(fmaxf(sB[0], sB[1]), fmaxf(sB[2], sB[3]));
            float mn = fmaxf(m_i[1], mx);
            float cr = __expf(m_i[1] - mn);
            float p[4], ps = 0.f;
            #pragma unroll
            for (int c = 0; c < 4; c++) { p[c] = __expf(sB[c] - mn); ps += p[c]; }
            l_i[1] = l_i[1] * cr + ps; m_i[1] = mn;
            #pragma unroll
            for (int f = 0; f < 8; f++)
                #pragma unroll
                for (int e = 0; e < 2; e++) {
                    int d = 8 * f + cq + e;
                    float acc = O[f][2 + e] * cr;
                    #pragma unroll
                    for (int c = 0; c < 4; c++) acc += p[c] * vg[c * 64 + d];
                    O[f][2 + e] = acc;
                }
        }
    }

    // ---- dense phase (qt==0): 256-thread S/O2, warp-0 merge ----
    if (do_glob) {
        __syncthreads();
        float* Sx  = Tsm;               // 4 x 1280
        float* Qf  = Tsm + 5120;        // 8 x 64
        float* O2  = Qf + 512;          // 4 x 64
        float* ML  = O2 + 256;          // 8
        float* wst = ML + 8;            // 8 warps x 4

        {
            const __nv_bfloat16* QCH = (const __nv_bfloat16*)(smc + AT_QCH);
            const __nv_bfloat16* QCL = (const __nv_bfloat16*)(smc + AT_QCL);
            const __nv_bfloat16* QRH = (const __nv_bfloat16*)(smc + AT_QRH);
            const __nv_bfloat16* QRL = (const __nv_bfloat16*)(smc + AT_QRL);
            #pragma unroll
            for (int u = 0; u < 2; u++) {
                int idx = tid * 2 + u;
                int r = idx >> 6, d = idx & 63;
                float v;
                if (r < 4)
                    v = __bfloat162float(QCH[r * 72 + d]) + __bfloat162float(QCL[r * 72 + d]);
                else
                    v = __bfloat162float(QRH[(r - 4) * 72 + d]) + __bfloat162float(QRL[(r - 4) * 72 + d]);
                Qf[idx] = v;
            }
        }
        __syncthreads();

        float mloc[4] = {-1e30f, -1e30f, -1e30f, -1e30f};
        #pragma unroll
        for (int u = 0; u < 5; u++) {
            int jloc = u * 256 + tid;
            int j = 256 + jloc;
            const float* kr = kg + j * 64;
            const float* rl = g_relk + (size_t)(j + 1535) * HD + h * DK;
            float a0 = 0.f, a1 = 0.f, a2 = 0.f, a3 = 0.f;
            #pragma unroll 8
            for (int d = 0; d < 64; d++) {
                float kv = kr[d];
                a0 += Qf[d] * kv        + Qf[256 + d] * rl[d];
                a1 += Qf[64 + d] * kv   + Qf[320 + d] * rl[d - HD];
                a2 += Qf[128 + d] * kv  + Qf[384 + d] * rl[d - 2 * HD];
                a3 += Qf[192 + d] * kv  + Qf[448 + d] * rl[d - 3 * HD];
            }
            Sx[jloc] = a0; Sx[1280 + jloc] = a1;
            Sx[2560 + jloc] = a2; Sx[3840 + jloc] = a3;
            mloc[0] = fmaxf(mloc[0], a0); mloc[1] = fmaxf(mloc[1], a1);
            mloc[2] = fmaxf(mloc[2], a2); mloc[3] = fmaxf(mloc[3], a3);
        }
        #pragma unroll
        for (int r = 0; r < 4; r++)
            #pragma unroll
            for (int off = 16; off >= 1; off >>= 1)
                mloc[r] = fmaxf(mloc[r], __shfl_xor_sync(0xffffffffu, mloc[r], off));
        if (lane == 0)
            #pragma unroll
            for (int r = 0; r < 4; r++) wst[wid * 4 + r] = mloc[r];
        __syncthreads();
        if (tid < 4) {
            float m = -1e30f;
            #pragma unroll
            for (int w = 0; w < 8; w++) m = fmaxf(m, wst[w * 4 + tid]);
            ML[tid] = m;
        }
        __syncthreads();
        float M2r[4] = {ML[0], ML[1], ML[2], ML[3]};
        float lloc[4] = {0.f, 0.f, 0.f, 0.f};
        #pragma unroll
        for (int u = 0; u < 5; u++) {
            int jloc = u * 256 + tid;
            #pragma unroll
            for (int r = 0; r < 4; r++) {
                float p = __expf(Sx[r * 1280 + jloc] - M2r[r]);
                Sx[r * 1280 + jloc] = p;
                lloc[r] += p;
            }
        }
        #pragma unroll
        for (int r = 0; r < 4; r++)
            #pragma unroll
            for (int off = 16; off >= 1; off >>= 1)
                lloc[r] += __shfl_xor_sync(0xffffffffu, lloc[r], off);
        if (lane == 0)
            #pragma unroll
            for (int r = 0; r < 4; r++) wst[wid * 4 + r] = lloc[r];
        __syncthreads();
        if (tid < 4) {
            float s = 0.f;
            #pragma unroll
            for (int w = 0; w < 8; w++) s += wst[w * 4 + tid];
            ML[4 + tid] = s;
        }
        __syncthreads();

        {
            int r = tid >> 6, d = tid & 63;
            const float* vp = vg + 256 * 64 + d;
            const float* px = Sx + r * 1280;
            float o = 0.f;
            #pragma unroll 4
            for (int jj = 0; jj < 1280; jj++)
                o += px[jj] * vp[jj * 64];
            O2[r * 64 + d] = o;
        }
        __syncthreads();

        if (wid == 0 && (lane >> 2) < 4) {
            int r = lane >> 2;
            float M2v = ML[r], L2v = ML[4 + r];
            float mn = fmaxf(m_i[0], M2v);
            float cA = __expf(m_i[0] - mn);
            float cB = __expf(M2v - mn);
            l_i[0] = l_i[0] * cA + L2v * cB;
            m_i[0] = mn;
            #pragma unroll
            for (int f = 0; f < 8; f++)
                #pragma unroll
                for (int e = 0; e < 2; e++) {
                    int d = 8 * f + cq + e;
                    O[f][e] = O[f][e] * cA + O2[r * 64 + d] * cB;
                }
        }
    }

    // ---- normalize + write packed ao (group 0 holds merged state) ----
    if (wg == 0) {
        float inv0 = 1.f / l_i[0], inv1 = 1.f / l_i[1];
        size_t o1 = (size_t)(b * NSEQ + i0 + i1) * 256 + h * 32;
        size_t o2 = (size_t)(b * NSEQ + i0 + i2) * 256 + h * 32;
        #pragma unroll
        for (int f = 0; f < 8; f++) {
            int j = (8 * f + cq) >> 1;
            u32 lo2, hi2;
            hi2 = pack2(O[f][0] * inv0, O[f][1] * inv0, lo2);
            p_aoh[o1 + j] = hi2; p_aol[o1 + j] = lo2;
            hi2 = pack2(O[f][2] * inv1, O[f][3] * inv1, lo2);
            p_aoh[o2 + j] = hi2; p_aol[o2 + j] = lo2;
        }
    }
}

// ================= launch =================
extern "C" void kernel_launch(void* const* d_in, const int* in_sizes, int n_in,
                              void* d_out, int out_size)
{
    const float* x    = (const float*)d_in[0];
    const float* Wq   = (const float*)d_in[1];
    const float* Wk   = (const float*)d_in[2];
    const float* Wv   = (const float*)d_in[3];
    const float* Wrel = (const float*)d_in[4];
    const float* rcb  = (const float*)d_in[5];
    const float* rpb  = (const float*)d_in[6];
    const float* Wo   = (const float*)d_in[7];
    const float* bo   = (const float*)d_in[8];
    const float* pe   = (const float*)d_in[9];
    float* out = (float*)d_out;

    cudaFuncSetAttribute(attn_kernel, cudaFuncAttributeMaxDynamicSharedMemorySize, ATTN_SMEM);
    cudaFuncSetAttribute(qkvrelk_tc, cudaFuncAttributeMaxDynamicSharedMemorySize, GEMM_SMEM);
    cudaFuncSetAttribute(out_tc,     cudaFuncAttributeMaxDynamicSharedMemorySize, GEMM_SMEM);

    pack_all<<<PACK_BLOCKS, 256>>>((const float4*)x, (const float4*)Wq, (const float4*)Wk,
                                   (const float4*)Wv, (const float4*)Wo, (const float4*)pe,
                                   (const float4*)Wrel);
    qkvrelk_tc<<<dim3(4, 24, 4), 256, GEMM_SMEM>>>(rcb, rpb);
    attn_kernel<<<dim3(16, 24), 256, ATTN_SMEM>>>();
    out_tc<<<dim3(12, 24), 256, GEMM_SMEM>>>(bo, out);
}